// round 9
// baseline (speedup 1.0000x reference)
#include <cuda_runtime.h>

// LinearInterpolation specialized for nk=13 knots, m=48 positions.
//   out[b, p, :] = lerp(value[b, seg(p), :], value[b, seg(p)+1, :], t(p))
//
// R9: warp-autonomous streaming. Kernel sits at the chip LTS ceiling
// (134 MB compulsory L2 traffic); the last uncoupled lever is removing all
// block-wide synchronization so LTS demand isn't block-quantized:
//  - each warp owns private 16-row tiles + a private 2-stage cp.async ring
//  - ordering via per-warp cp.async.wait_group + __syncwarp only (no BAR.SYNC
//    in the hot loop)
//  - occupancy 94% (192 thr x 10 blocks/SM, 19.9KB smem)
//  - coalesced 128B stores per (pass,k): 4 rows x 8 lanes contiguous
//  - 3-LDS.64 gather (knot gaps >= 3) + packed fma.rn.f32x2 kept

typedef unsigned long long ull;

__device__ __forceinline__ ull fma2(ull a, ull b, ull c) {
    ull d;
    asm("fma.rn.f32x2 %0, %1, %2, %3;" : "=l"(d) : "l"(a), "l"(b), "l"(c));
    return d;
}
__device__ __forceinline__ ull pack2(float lo, float hi) {
    ull d;
    asm("mov.b64 %0, {%1, %2};" : "=l"(d) : "f"(lo), "f"(hi));
    return d;
}
__device__ __forceinline__ void cp16(unsigned s, const void* g) {
    asm volatile("cp.async.cg.shared.global [%0], [%1], 16;" :: "r"(s), "l"(g));
}
__device__ __forceinline__ void cp8(unsigned s, const void* g) {
    asm volatile("cp.async.ca.shared.global [%0], [%1], 8;" :: "r"(s), "l"(g));
}
__device__ __forceinline__ void cp_commit() { asm volatile("cp.async.commit_group;"); }
template <int N>
__device__ __forceinline__ void cp_wait() {
    asm volatile("cp.async.wait_group %0;" :: "n"(N));
}

// ---- specialized path: nk=13, m=48 ----
#define NK    13
#define FR    26               // floats per input row
#define FR2   13               // float2 (ull) per input row
#define M     48
#define WARPS 6
#define NTHREADS (WARPS * 32)  // 192
#define WROWS 16               // rows per warp-tile
#define WSTAGES 2
#define WTILE_F (WROWS * FR)   // 416 floats = 1664 B
#define WTILE_F4 (WTILE_F / 4) // 104 float4 loads per tile

__global__ __launch_bounds__(NTHREADS)
void lerp_spec_kernel(const int*    __restrict__ index,
                      const float4* __restrict__ v4,
                      float4*       __restrict__ out4,
                      int batch)
{
    __shared__ __align__(16) float s_in[WARPS][WSTAGES][WTILE_F]; // 19968 B
    __shared__ int   s_seg[M];
    __shared__ float s_t[M];

    const int tid  = threadIdx.x;
    const int wid  = tid >> 5;            // warp in block, 0..5
    const int lane = tid & 31;
    const int r    = lane >> 3;           // row-group within pass, 0..3
    const int q    = lane & 7;            // column-octant, 0..7

    // ---- seg / t precompute (once per block) ----
    if (tid < M) {
        const int p = index[0] + 1 + tid;
        int seg = 0;
        #pragma unroll
        for (int i = 1; i < NK; ++i)
            if (index[i] < p) seg = i;
        const float x0 = (float)index[seg];
        const float x1 = (float)index[seg + 1];
        s_seg[tid] = seg;
        s_t[tid]   = ((float)p - x0) / (x1 - x0);
    }
    __syncthreads();                      // only block-wide barrier

    // ---- per-thread invariants: this thread covers tx = q + 8k, k=0..2 ----
    int  sA[3], sB[3];
    bool same[3];
    ull  ttA[3], ttB[3];
    #pragma unroll
    for (int k = 0; k < 3; ++k) {
        const int p0 = (q + 8 * k) << 1;
        sA[k]   = s_seg[p0];
        sB[k]   = s_seg[p0 + 1];
        same[k] = (sB[k] == sA[k]);       // knot gaps >= 3 => sB in {sA, sA+1}
        ttA[k]  = pack2(s_t[p0],     s_t[p0]);
        ttB[k]  = pack2(s_t[p0 + 1], s_t[p0 + 1]);
    }
    const ull M1 = 0xBF800000BF800000ULL; // (-1.f, -1.f)

    const float* gin = reinterpret_cast<const float*>(v4);
    const int nT     = (batch + WROWS - 1) / WROWS;       // warp-tiles total
    const int nW     = gridDim.x * WARPS;                 // warps total
    const int gwarp  = blockIdx.x * WARPS + wid;

    // per-warp prefetch of tile t into private stage buffer
    auto prefetch = [&](int t, int stage) {
        const int r0      = t * WROWS;
        const int nfloats = min(WROWS, batch - r0) * FR;  // 416 full
        const int nf4     = nfloats >> 2;                 // 104 full
        const float* g    = gin + (long long)r0 * FR;
        unsigned s = (unsigned)__cvta_generic_to_shared(&s_in[wid][stage][0]);
        #pragma unroll
        for (int j = 0; j < 4; ++j) {                     // 104/32 -> <=4
            const int i = lane + j * 32;
            if (i < nf4) cp16(s + i * 16, g + i * 4);
        }
        if (lane == 0 && (nfloats & 3))
            cp8(s + nf4 * 16, g + nf4 * 4);
        cp_commit();
    };

    // ---- prologue: fill this warp's 2-stage ring ----
    {
        int t = gwarp;
        #pragma unroll
        for (int sb = 0; sb < WSTAGES; ++sb) {
            if (t < nT) { prefetch(t, sb); t += nW; }
            else cp_commit();             // keep per-thread group count aligned
        }
    }

    int stage = 0;
    for (int t = gwarp; t < nT; t += nW) {
        cp_wait<WSTAGES - 1>();           // oldest group (this stage) landed
        __syncwarp();                     // cross-lane visibility of cp.async

        const int row0  = t * WROWS;
        const int nrows = min(WROWS, batch - row0);
        const ull* sb   = reinterpret_cast<const ull*>(&s_in[wid][stage][0]);

        #pragma unroll
        for (int pass = 0; pass < WROWS / 4; ++pass) {
            const int row = pass * 4 + r;
            if (row >= nrows) break;
            const ull* rp = sb + row * FR2;
            const long long ob = (long long)(row0 + row) * 24 + q;

            #pragma unroll
            for (int k = 0; k < 3; ++k) {
                const ull c0 = rp[sA[k]];
                const ull c1 = rp[sA[k] + 1];
                const ull c2 = rp[sB[k] + 1];
                const ull b0 = same[k] ? c0 : c1;

                const ull oA = fma2(fma2(c0, M1, c1), ttA[k], c0);
                const ull oB = fma2(fma2(b0, M1, c2), ttB[k], b0);

                float4 o;
                asm("mov.b64 {%0, %1}, %2;" : "=f"(o.x), "=f"(o.y) : "l"(oA));
                asm("mov.b64 {%0, %1}, %2;" : "=f"(o.z), "=f"(o.w) : "l"(oB));
                out4[ob + 8 * k] = o;     // coalesced: 8 lanes x 16B contiguous
            }
        }
        __syncwarp();                     // all lanes done reading this stage

        const int nxt = t + WSTAGES * nW; // refill this stage 2 tiles ahead
        if (nxt < nT) prefetch(nxt, stage);
        else cp_commit();                 // keep wait_group accounting aligned
        stage ^= 1;
    }
}

// ---- generic fallback (any nk/m, m even) ----
#define GTHREADS 256
__global__ __launch_bounds__(GTHREADS)
void lerp_generic_kernel(const int* __restrict__ index,
                         const float* __restrict__ value,
                         float2* __restrict__ out2,
                         int batch, int nk, int m)
{
    __shared__ int   s_seg[256];
    __shared__ float s_t[256];
    const int tid = threadIdx.x;
    if (tid < m) {
        const int p = index[0] + 1 + tid;
        int seg = 0;
        for (int i = 1; i < nk; ++i)
            if (index[i] < p) seg = i;
        const float x0 = (float)index[seg];
        const float x1 = (float)index[seg + 1];
        s_seg[tid] = seg;
        s_t[tid]   = ((float)p - x0) / (x1 - x0);
    }
    __syncthreads();
    const long long total = (long long)batch * m;
    for (long long i = (long long)blockIdx.x * GTHREADS + tid; i < total;
         i += (long long)gridDim.x * GTHREADS) {
        const int pp = (int)(i % m);
        const long long b = i / m;
        const int seg = s_seg[pp];
        const float t = s_t[pp];
        const float2* r = reinterpret_cast<const float2*>(value) + b * nk;
        const float2 v0 = r[seg], v1 = r[seg + 1];
        float2 o;
        o.x = fmaf(v1.x - v0.x, t, v0.x);
        o.y = fmaf(v1.y - v0.y, t, v0.y);
        out2[i] = o;
    }
}

extern "C" void kernel_launch(void* const* d_in, const int* in_sizes, int n_in,
                              void* d_out, int out_size)
{
    const int*   index = (const int*)d_in[0];
    const float* value = (const float*)d_in[1];

    const int nk    = in_sizes[0];                   // 13
    const int batch = in_sizes[1] / (nk * 2);        // 262144
    const int m     = out_size / (batch * 2);        // 48

    if (nk == NK && m == M) {
        const int nT   = (batch + WROWS - 1) / WROWS;            // 16384
        const int need = (nT + WARPS - 1) / WARPS;               // blocks needed
        const int grid = need < 1480 ? need : 1480;              // 10 blocks/SM
        lerp_spec_kernel<<<grid, NTHREADS>>>(
            index,
            reinterpret_cast<const float4*>(value),
            reinterpret_cast<float4*>(d_out),
            batch);
    } else {
        const long long total = (long long)batch * m;
        int grid = (int)min((total + GTHREADS - 1) / GTHREADS, (long long)65535 * 8);
        lerp_generic_kernel<<<grid, GTHREADS>>>(
            index, value, reinterpret_cast<float2*>(d_out), batch, nk, m);
    }
}

// round 10
// speedup vs baseline: 1.1738x; 1.1738x over previous
#include <cuda_runtime.h>

// LinearInterpolation specialized for nk=13 knots, m=48 positions.
//   out[b, p, :] = lerp(value[b, seg(p), :], value[b, seg(p)+1, :], t(p))
//
// R10 = R8 (best reported: 23.0us) + streaming stores (st.global.cs).
// Diagnosis: steady-state graph-replay time = 128MB compulsory DRAM bytes /
// realized DRAM BW (~5.6 TB/s). Plain STG leaves the 101MB output stream
// dirty in L2 -> bursty capacity writebacks colliding with the next
// iteration's reads. Evict-first stores (__stcs) push output through L2
// promptly and keep the read stream resident, raising realized DRAM
// efficiency. Everything else identical to R8:
//  - ROWS=64 tiles, 3-stage cp.async input pipeline, persistent grid 1480
//  - 3-LDS.64 gather (knot gaps >= 3) + packed fma.rn.f32x2

typedef unsigned long long ull;

__device__ __forceinline__ ull fma2(ull a, ull b, ull c) {
    ull d;
    asm("fma.rn.f32x2 %0, %1, %2, %3;" : "=l"(d) : "l"(a), "l"(b), "l"(c));
    return d;
}
__device__ __forceinline__ ull pack2(float lo, float hi) {
    ull d;
    asm("mov.b64 %0, {%1, %2};" : "=l"(d) : "f"(lo), "f"(hi));
    return d;
}
__device__ __forceinline__ void cp16(unsigned s, const void* g) {
    asm volatile("cp.async.cg.shared.global [%0], [%1], 16;" :: "r"(s), "l"(g));
}
__device__ __forceinline__ void cp8(unsigned s, const void* g) {
    asm volatile("cp.async.ca.shared.global [%0], [%1], 8;" :: "r"(s), "l"(g));
}
__device__ __forceinline__ void cp_commit() { asm volatile("cp.async.commit_group;"); }
template <int N>
__device__ __forceinline__ void cp_wait() {
    asm volatile("cp.async.wait_group %0;" :: "n"(N));
}

// ---- specialized path: nk=13, m=48 ----
#define NK    13
#define FR    26               // floats per input row
#define FR2   13               // float2 (ull) per input row
#define M     48
#define TXc   24               // float4 outputs per row
#define TYc   8
#define NTHREADS (TXc * TYc)   // 192
#define ROWS  64
#define KITER (ROWS / TYc)     // 8
#define STAGES 3

__global__ __launch_bounds__(NTHREADS)
void lerp_spec_kernel(const int*    __restrict__ index,
                      const float4* __restrict__ v4,
                      float4*       __restrict__ out4,
                      int batch)
{
    __shared__ __align__(16) float s_in[STAGES][ROWS * FR];  // 3 x 6656 B
    __shared__ int   s_seg[M];
    __shared__ float s_t[M];

    const int tx  = threadIdx.x;          // 0..23
    const int ty  = threadIdx.y;          // 0..7
    const int tid = ty * TXc + tx;

    const int nTiles = (batch + ROWS - 1) / ROWS;
    if (blockIdx.x >= nTiles) return;     // uniform per block

    // ---- seg / t precompute (once per block) ----
    if (tid < M) {
        const int p = index[0] + 1 + tid;
        int seg = 0;
        #pragma unroll
        for (int i = 1; i < NK; ++i)
            if (index[i] < p) seg = i;
        const float x0 = (float)index[seg];
        const float x1 = (float)index[seg + 1];
        s_seg[tid] = seg;
        s_t[tid]   = ((float)p - x0) / (x1 - x0);
    }

    const float* gin = reinterpret_cast<const float*>(v4);

    // stream tile t's input slab into stage buffer `buf` (one commit group)
    auto prefetch = [&](int t, int buf) {
        const int r0      = t * ROWS;
        const int nfloats = min(ROWS, batch - r0) * FR;   // 1664 full
        const int nf4     = nfloats >> 2;                 // 416 full
        const float* g    = gin + (long long)r0 * FR;
        unsigned s = (unsigned)__cvta_generic_to_shared(&s_in[buf][0]);
        #pragma unroll
        for (int j = 0; j < 3; ++j) {                     // 416/192 <= 3
            const int i = tid + j * NTHREADS;
            if (i < nf4) cp16(s + i * 16, g + i * 4);
        }
        if (tid == 0 && (nfloats & 3))
            cp8(s + nf4 * 16, g + nf4 * 4);
        cp_commit();
    };

    // ---- prologue: fill the pipeline ----
    int nextTile = blockIdx.x;
    #pragma unroll
    for (int sb = 0; sb < STAGES; ++sb) {
        if (nextTile < nTiles) { prefetch(nextTile, sb); nextTile += gridDim.x; }
        else cp_commit();                 // keep group accounting consistent
    }
    __syncthreads();                      // s_seg / s_t visible

    // ---- per-thread loop invariants ----
    const int  p0   = tx << 1;
    const int  sA   = s_seg[p0];
    const int  sB   = s_seg[p0 + 1];
    const bool same = (sB == sA);         // knot gaps >= 3 => sB in {sA, sA+1}
    const ull  ttA  = pack2(s_t[p0],     s_t[p0]);
    const ull  ttB  = pack2(s_t[p0 + 1], s_t[p0 + 1]);
    const ull  M1   = 0xBF800000BF800000ULL;   // (-1.f, -1.f)

    int c = 0;
    for (int tile = blockIdx.x; tile < nTiles; tile += gridDim.x) {
        cp_wait<STAGES - 1>();            // oldest stage (buf c) ready
        __syncthreads();

        const int row0  = tile * ROWS;
        const int nrows = min(ROWS, batch - row0);
        const ull* rb   = reinterpret_cast<const ull*>(&s_in[c][0]) + ty * FR2;
        const long long ob = (long long)(row0 + ty) * TXc + tx;

        #pragma unroll
        for (int k = 0; k < KITER; ++k) {
            const int row = ty + k * TYc;
            if (row >= nrows) break;

            const ull* r = rb + k * (TYc * FR2);
            const ull c0 = r[sA];
            const ull c1 = r[sA + 1];
            const ull c2 = r[sB + 1];
            const ull b0 = same ? c0 : c1;

            const ull oA = fma2(fma2(c0, M1, c1), ttA, c0);
            const ull oB = fma2(fma2(b0, M1, c2), ttB, b0);

            float4 o;
            asm("mov.b64 {%0, %1}, %2;" : "=f"(o.x), "=f"(o.y) : "l"(oA));
            asm("mov.b64 {%0, %1}, %2;" : "=f"(o.z), "=f"(o.w) : "l"(oB));
            __stcs(&out4[ob + (long long)k * (TYc * TXc)], o);  // STG.CS evict-first
        }
        __syncthreads();                  // readers of buf c done before refill

        if (nextTile < nTiles) { prefetch(nextTile, c); nextTile += gridDim.x; }
        else cp_commit();                 // keep wait_group accounting aligned
        c = (c + 1 == STAGES) ? 0 : c + 1;
    }
}

// ---- generic fallback (any nk/m, m even) ----
#define GTHREADS 256
__global__ __launch_bounds__(GTHREADS)
void lerp_generic_kernel(const int* __restrict__ index,
                         const float* __restrict__ value,
                         float2* __restrict__ out2,
                         int batch, int nk, int m)
{
    __shared__ int   s_seg[256];
    __shared__ float s_t[256];
    const int tid = threadIdx.x;
    if (tid < m) {
        const int p = index[0] + 1 + tid;
        int seg = 0;
        for (int i = 1; i < nk; ++i)
            if (index[i] < p) seg = i;
        const float x0 = (float)index[seg];
        const float x1 = (float)index[seg + 1];
        s_seg[tid] = seg;
        s_t[tid]   = ((float)p - x0) / (x1 - x0);
    }
    __syncthreads();
    const long long total = (long long)batch * m;
    for (long long i = (long long)blockIdx.x * GTHREADS + tid; i < total;
         i += (long long)gridDim.x * GTHREADS) {
        const int pp = (int)(i % m);
        const long long b = i / m;
        const int seg = s_seg[pp];
        const float t = s_t[pp];
        const float2* r = reinterpret_cast<const float2*>(value) + b * nk;
        const float2 v0 = r[seg], v1 = r[seg + 1];
        float2 o;
        o.x = fmaf(v1.x - v0.x, t, v0.x);
        o.y = fmaf(v1.y - v0.y, t, v0.y);
        out2[i] = o;
    }
}

extern "C" void kernel_launch(void* const* d_in, const int* in_sizes, int n_in,
                              void* d_out, int out_size)
{
    const int*   index = (const int*)d_in[0];
    const float* value = (const float*)d_in[1];

    const int nk    = in_sizes[0];                   // 13
    const int batch = in_sizes[1] / (nk * 2);        // 262144
    const int m     = out_size / (batch * 2);        // 48

    if (nk == NK && m == M) {
        const int nTiles = (batch + ROWS - 1) / ROWS;       // 4096
        const int grid   = nTiles < 1480 ? nTiles : 1480;   // 10 blocks/SM x 148
        dim3 block(TXc, TYc);
        lerp_spec_kernel<<<grid, block>>>(
            index,
            reinterpret_cast<const float4*>(value),
            reinterpret_cast<float4*>(d_out),
            batch);
    } else {
        const long long total = (long long)batch * m;
        int grid = (int)min((total + GTHREADS - 1) / GTHREADS, (long long)65535 * 8);
        lerp_generic_kernel<<<grid, GTHREADS>>>(
            index, value, reinterpret_cast<float2*>(d_out), batch, nk, m);
    }
}